// round 9
// baseline (speedup 1.0000x reference)
#include <cuda_runtime.h>
#include <cuda_fp16.h>
#include <math.h>

#define T_DIM 2048
#define B_DIM 1024
#define A_DIM 4
#define D_DIM 128
#define P_DIM 256
#define TC    32
#define NCH   (T_DIM / TC)
#define LDB   272            // tile row stride in bytes (136 halves)
#define NLOGIT (T_DIM * B_DIM * A_DIM)

// SMEM layout (bytes)
#define OFF_SA    0          // 2 x 128 float2             [0,2048)
#define OFF_BETA  2048       // 128 floats                 [2048,2560)
#define OFF_LPART 2560       // 2 x 128 floats             [2560,3584)
#define OFF_CT    4608       // 136 x 272 = 36992          [4608,41600)
#define OFF_HS0   41600      // 128 x 272 = 34816
#define OFF_HS1   76416
#define OFF_QS0   111232
#define OFF_QS1   146048
#define SMEM_BYTES 180864
#define BUFD      34816u     // HS1-HS0 == QS1-QS0

// named barriers: 1,2 = FULL[buf], 3,4 = EMPTY[buf], 5 = consumer EPI, 6 = producer
#define BAR_SYNC(id, cnt)   asm volatile("bar.sync %0, %1;"   :: "r"(id), "r"(cnt) : "memory")
#define BAR_ARRIVE(id, cnt) asm volatile("bar.arrive %0, %1;" :: "r"(id), "r"(cnt) : "memory")

// scratch: per (b,t,a): (s = r*a, a)
__device__ float2 g_SA[(size_t)B_DIM * T_DIM * A_DIM];

static __device__ __forceinline__ float nan0(float x) { return (x == x) ? x : 0.0f; }
static __device__ __forceinline__ float clipf(float x, float lo, float hi) {
    return fminf(fmaxf(x, lo), hi);
}
static __device__ __forceinline__ unsigned smem_u32(const void* p) {
    return (unsigned)__cvta_generic_to_shared(p);
}

__global__ void prep_kernel(const float* __restrict__ inp) {
    int gid = blockIdx.x * blockDim.x + threadIdx.x;
    if (gid >= T_DIM * B_DIM) return;
    int b = gid % B_DIM;
    int t = gid / B_DIM;
    const float* row = inp + ((size_t)t * B_DIM + b) * 9;
    float2* o = g_SA + ((size_t)b * T_DIM + t) * A_DIM;
#pragma unroll
    for (int a = 0; a < A_DIM; a++) {
        float act = nan0(row[a]);
        float r   = nan0(row[4 + a]);
        o[a] = make_float2(r * act, act);
    }
}

static __device__ __forceinline__ void mma16816(float* acc, const unsigned* a,
                                                unsigned b0, unsigned b1) {
    asm volatile(
        "mma.sync.aligned.m16n8k16.row.col.f32.f16.f16.f32 "
        "{%0,%1,%2,%3}, {%4,%5,%6,%7}, {%8,%9}, {%0,%1,%2,%3};\n"
        : "+f"(acc[0]), "+f"(acc[1]), "+f"(acc[2]), "+f"(acc[3])
        : "r"(a[0]), "r"(a[1]), "r"(a[2]), "r"(a[3]), "r"(b0), "r"(b1));
}
static __device__ __forceinline__ void ldsm4(unsigned* r, unsigned addr) {
    asm volatile(
        "ldmatrix.sync.aligned.m8n8.x4.shared.b16 {%0,%1,%2,%3}, [%4];\n"
        : "=r"(r[0]), "=r"(r[1]), "=r"(r[2]), "=r"(r[3]) : "r"(addr));
}
static __device__ __forceinline__ void ldsm2(unsigned* r, unsigned addr) {
    asm volatile(
        "ldmatrix.sync.aligned.m8n8.x2.shared.b16 {%0,%1}, [%2];\n"
        : "=r"(r[0]), "=r"(r[1]) : "r"(addr));
}

// ---------------------------------------------------------------------------
// Warp-specialized: producers (w4-7) scan -> double-buffered f16 tiles;
// consumers (w0-3) GEMM U = H x Ct^T (+kappa row) + epilogue.  1 CTA/SM.
// ---------------------------------------------------------------------------
__global__ void __launch_bounds__(256, 1) gql_main(
    const float* __restrict__ inp,
    const float* __restrict__ phi_raw,  const float* __restrict__ chi_raw,
    const float* __restrict__ beta_raw, const float* __restrict__ kappa_raw,
    const float* __restrict__ C_raw,    float* __restrict__ out) {
    extern __shared__ char sm[];
    float2* sa_s   = (float2*)(sm + OFF_SA);
    float*  beta_s = (float*)(sm + OFF_BETA);
    float*  lpart  = (float*)(sm + OFF_LPART);
    __half* Ct     = (__half*)(sm + OFF_CT);

    const int b    = blockIdx.x;
    const int tid  = threadIdx.x;
    const int lane = tid & 31;
    const int w    = tid >> 5;
    const int g    = lane >> 2;
    const int tg   = lane & 3;
    const int pid  = min(max((int)nan0(__ldg(inp + (size_t)b * 9 + 8)), 0), P_DIM - 1);

    // ---- one-time SMEM setup (all threads) ----
    for (int i = tid; i < 8 * LDB / 4; i += 256)
        ((unsigned*)(sm + OFF_CT + 128 * LDB))[i] = 0;
    __syncthreads();   // zeroing complete before kappa lands in row 128
    if (tid < 128) {
        float br = beta_raw[pid * D_DIM + tid];
        float sp = fmaxf(br, 0.0f) + log1pf(expf(-fabsf(br)));
        beta_s[tid] = clipf(sp, 0.1f, 10.0f);
        Ct[128 * 136 + tid] =
            __float2half(clipf(kappa_raw[pid * D_DIM + tid], -10.0f, 10.0f));
    }
    for (int i = tid; i < D_DIM * D_DIM; i += 256) {
        int d = i >> 7, e = i & 127;
        Ct[e * 136 + d] = __float2half(clipf(C_raw[(size_t)pid * (D_DIM * D_DIM) + i],
                                             -10.0f, 10.0f));
    }
    const float2* sa_src = g_SA + (size_t)b * T_DIM * A_DIM;
    if (tid < 128) sa_s[tid] = sa_src[tid];   // preload chunk 0 into buf 0
    __syncthreads();

    if (w >= 4) {
        // ================= producers: sequential scan =================
        const int st = tid - 128;
        const int wa = st >> 5;          // action index (one per warp)
        const int d0 = lane * 4;         // this thread's 4 d-values

        float4 ph4 = *(const float4*)(phi_raw + pid * D_DIM + d0);
        float4 ch4 = *(const float4*)(chi_raw + pid * D_DIM + d0);
        float phi[4], chi[4], omp[4], omc[4], q[4], h[4];
        {
            const float* pp = (const float*)&ph4;
            const float* cc = (const float*)&ch4;
#pragma unroll
            for (int i = 0; i < 4; i++) {
                phi[i] = clipf(1.0f / (1.0f + expf(-pp[i])), 0.01f, 0.99f);
                chi[i] = clipf(1.0f / (1.0f + expf(-cc[i])), 0.01f, 0.99f);
                omp[i] = 1.0f - phi[i];
                omc[i] = 1.0f - chi[i];
                q[i] = 0.5f; h[i] = 0.0f;
            }
        }

        for (int c = 0; c < NCH; c++) {
            const int cb = c & 1;
            float2 nxt;
            const bool pf = (c + 1 < NCH);
            if (pf) nxt = __ldg(sa_src + (c + 1) * 128 + st);
            if (c >= 2) BAR_SYNC(3 + cb, 256);          // EMPTY[cb]

            char* Hb = sm + (cb ? OFF_HS1 : OFF_HS0);
            char* Qb = sm + (cb ? OFF_QS1 : OFF_QS0);
            const float2* sab = sa_s + cb * 128;
#pragma unroll 4
            for (int tt = 0; tt < TC; tt++) {
                float2 sa = sab[tt * 4 + wa];
                float s = sa.x, a = sa.y;
#pragma unroll
                for (int i = 0; i < 4; i++) {
                    q[i] = omp[i] * q[i] + phi[i] * s;
                    h[i] = omc[i] * h[i] + chi[i] * a;
                }
                int row = tt * 4 + wa;
                __half2 hA = __floats2half2_rn(h[0], h[1]);
                __half2 hB = __floats2half2_rn(h[2], h[3]);
                __half2 qA = __floats2half2_rn(q[0], q[1]);
                __half2 qB = __floats2half2_rn(q[2], q[3]);
                uint2 hv = make_uint2(*(unsigned*)&hA, *(unsigned*)&hB);
                uint2 qv = make_uint2(*(unsigned*)&qA, *(unsigned*)&qB);
                *(uint2*)(Hb + row * LDB + lane * 8) = hv;
                *(uint2*)(Qb + row * LDB + lane * 8) = qv;
            }
            if (pf) sa_s[(cb ^ 1) * 128 + st] = nxt;
            BAR_SYNC(6, 128);                           // producer-internal
            BAR_ARRIVE(1 + cb, 256);                    // FULL[cb]
        }

        // final q, h: shape (B, A, D)
        float* out_q = out + (size_t)NLOGIT;
        float* out_h = out_q + B_DIM * A_DIM * D_DIM;
        ((float4*)out_q)[(b * A_DIM + wa) * 32 + lane] =
            make_float4(q[0], q[1], q[2], q[3]);
        ((float4*)out_h)[(b * A_DIM + wa) * 32 + lane] =
            make_float4(h[0], h[1], h[2], h[3]);
    } else {
        // ================= consumers: GEMM + epilogue =================
        const int mw  = w & 1;           // 64-row group
        const int nwc = w >> 1;          // 64-col group
        const bool kon = (nwc == 1);     // kappa tile on these warps

        unsigned amt[4], bb[4], bbx, qbase;
        {
            unsigned hs0 = smem_u32(sm + OFF_HS0);
            int r  = lane & 15;
            int cb16 = (lane & 16) ? 16 : 0;
#pragma unroll
            for (int mt = 0; mt < 4; mt++)
                amt[mt] = hs0 + (unsigned)((mw * 64 + mt * 16 + r) * LDB + cb16);

            unsigned ct0 = smem_u32(Ct);
            int brow = (lane & 7) + ((lane & 16) ? 8 : 0);
            int bcol = (lane & 8) ? 16 : 0;
#pragma unroll
            for (int pr = 0; pr < 4; pr++)
                bb[pr] = ct0 + (unsigned)((nwc * 64 + pr * 16 + brow) * LDB + bcol);
            bbx = ct0 + (unsigned)((128 + (lane & 7)) * LDB + ((lane & 8) ? 16 : 0));

            qbase = smem_u32(sm + OFF_QS0) + (unsigned)((mw * 64 + lane) * LDB);
        }

        for (int c = 0; c < NCH; c++) {
            const int cb = c & 1;
            const unsigned delta = cb ? BUFD : 0u;
            BAR_SYNC(1 + cb, 256);                      // FULL[cb]

            float acc[4][8][4];
            float accx[4][4];
#pragma unroll
            for (int mt = 0; mt < 4; mt++) {
#pragma unroll
                for (int nt = 0; nt < 8; nt++)
#pragma unroll
                    for (int i = 0; i < 4; i++) acc[mt][nt][i] = 0.0f;
#pragma unroll
                for (int i = 0; i < 4; i++) accx[mt][i] = 0.0f;
            }

#pragma unroll
            for (int ks = 0; ks < 8; ks++) {
                unsigned bf[4][4], bfx[2];
#pragma unroll
                for (int pr = 0; pr < 4; pr++) ldsm4(bf[pr], bb[pr] + ks * 32);
                if (kon) ldsm2(bfx, bbx + ks * 32);
#pragma unroll
                for (int mt = 0; mt < 4; mt++) {
                    unsigned af[4];
                    ldsm4(af, amt[mt] + delta + ks * 32);
#pragma unroll
                    for (int pr = 0; pr < 4; pr++) {
                        mma16816(acc[mt][2 * pr],     af, bf[pr][0], bf[pr][1]);
                        mma16816(acc[mt][2 * pr + 1], af, bf[pr][2], bf[pr][3]);
                    }
                    if (kon) mma16816(accx[mt], af, bfx[0], bfx[1]);
                }
            }

            // epilogue: pl[mt] = sum over this warp's 64 cols
            float pl0[4] = {0.f, 0.f, 0.f, 0.f}, pl1[4] = {0.f, 0.f, 0.f, 0.f};
#pragma unroll
            for (int nt = 0; nt < 8; nt++) {
                int col = nwc * 64 + nt * 8;
                float2 bet = make_float2(beta_s[col + 2 * tg], beta_s[col + 2 * tg + 1]);
                unsigned qfA[4], qfB[4];
                ldsm4(qfA, qbase + delta + (unsigned)(col * 2));
                ldsm4(qfB, qbase + delta + (unsigned)(32 * LDB + col * 2));
#pragma unroll
                for (int mt = 0; mt < 4; mt++) {
                    const unsigned* qf = (mt < 2) ? qfA : qfB;
                    float2 qv0 = __half22float2(*(__half2*)&qf[2 * (mt & 1)]);
                    float2 qv1 = __half22float2(*(__half2*)&qf[2 * (mt & 1) + 1]);
                    pl0[mt] += (acc[mt][nt][0] + bet.x) * qv0.x
                             + (acc[mt][nt][1] + bet.y) * qv0.y;
                    pl1[mt] += (acc[mt][nt][2] + bet.x) * qv1.x
                             + (acc[mt][nt][3] + bet.y) * qv1.y;
                }
            }

#pragma unroll
            for (int mt = 0; mt < 4; mt++) {
                if (kon && tg == 0) {
                    pl0[mt] += accx[mt][0];
                    pl1[mt] += accx[mt][2];
                }
                pl0[mt] += __shfl_xor_sync(0xffffffffu, pl0[mt], 1);
                pl0[mt] += __shfl_xor_sync(0xffffffffu, pl0[mt], 2);
                pl1[mt] += __shfl_xor_sync(0xffffffffu, pl1[mt], 1);
                pl1[mt] += __shfl_xor_sync(0xffffffffu, pl1[mt], 2);
                if (tg == 0) {
                    int r0 = mw * 64 + mt * 16 + g;
                    lpart[nwc * 128 + r0]     = pl0[mt];
                    lpart[nwc * 128 + r0 + 8] = pl1[mt];
                }
            }
            BAR_SYNC(5, 128);                           // consumer-internal (lpart)

            {   // all 128 consumer threads combine + store logits for chunk c
                float lg = lpart[tid] + lpart[128 + tid];
                int tt = tid >> 2, a = tid & 3;
                out[((size_t)(c * TC + tt) * B_DIM + b) * A_DIM + a] = lg;
            }
            BAR_ARRIVE(3 + cb, 256);                    // EMPTY[cb]
        }
    }
}

extern "C" void kernel_launch(void* const* d_in, const int* in_sizes, int n_in,
                              void* d_out, int out_size) {
    const float* inp       = (const float*)d_in[0];
    const float* phi_raw   = (const float*)d_in[1];
    const float* chi_raw   = (const float*)d_in[2];
    const float* beta_raw  = (const float*)d_in[3];
    const float* kappa_raw = (const float*)d_in[4];
    const float* C_raw     = (const float*)d_in[5];
    float* out = (float*)d_out;

    cudaFuncSetAttribute(gql_main, cudaFuncAttributeMaxDynamicSharedMemorySize,
                         SMEM_BYTES);

    prep_kernel<<<(T_DIM * B_DIM + 255) / 256, 256>>>(inp);
    gql_main<<<B_DIM, 256, SMEM_BYTES>>>(inp, phi_raw, chi_raw, beta_raw,
                                         kappa_raw, C_raw, out);
}

// round 12
// speedup vs baseline: 1.0500x; 1.0500x over previous
#include <cuda_runtime.h>
#include <cuda_fp16.h>
#include <math.h>

#define T_DIM 2048
#define B_DIM 1024
#define A_DIM 4
#define D_DIM 128
#define P_DIM 256
#define TC    16
#define NCH   (T_DIM / TC)     // 128 chunks of 64 rows
#define LDB   272              // tile row stride in bytes (136 halves)
#define NLOGIT (T_DIM * B_DIM * A_DIM)

// SMEM layout (bytes)
#define OFF_SA    0            // 2 x 64 float2   [0,1024)
#define OFF_BETA  1024         // 128 floats      [1024,1536)
#define OFF_KAPPA 1536         // 128 floats      [1536,2048)
#define OFF_LPART 2048         // 4 x 64 floats   [2048,3072)
#define OFF_HS0   4096         // 64 x 272 = 17408
#define OFF_HS1   21504
#define OFF_QS0   38912
#define OFF_QS1   56320
#define SMEM_BYTES 73728
#define BUFD      17408u
#define OFF_CT    4096         // C staging, ALIASES the tile buffers (init-only)

// scratch: per (b,t,a): (s = r*a, a)
__device__ float2 g_SA[(size_t)B_DIM * T_DIM * A_DIM];

static __device__ __forceinline__ float nan0(float x) { return (x == x) ? x : 0.0f; }
static __device__ __forceinline__ float clipf(float x, float lo, float hi) {
    return fminf(fmaxf(x, lo), hi);
}
static __device__ __forceinline__ unsigned smem_u32(const void* p) {
    return (unsigned)__cvta_generic_to_shared(p);
}

__global__ void prep_kernel(const float* __restrict__ inp) {
    int gid = blockIdx.x * blockDim.x + threadIdx.x;
    if (gid >= T_DIM * B_DIM) return;
    int b = gid % B_DIM;
    int t = gid / B_DIM;
    const float* row = inp + ((size_t)t * B_DIM + b) * 9;
    float2* o = g_SA + ((size_t)b * T_DIM + t) * A_DIM;
#pragma unroll
    for (int a = 0; a < A_DIM; a++) {
        float act = nan0(row[a]);
        float r   = nan0(row[4 + a]);
        o[a] = make_float2(r * act, act);
    }
}

static __device__ __forceinline__ void mma16816(float* acc, const unsigned* a,
                                                unsigned b0, unsigned b1) {
    asm volatile(
        "mma.sync.aligned.m16n8k16.row.col.f32.f16.f16.f32 "
        "{%0,%1,%2,%3}, {%4,%5,%6,%7}, {%8,%9}, {%0,%1,%2,%3};\n"
        : "+f"(acc[0]), "+f"(acc[1]), "+f"(acc[2]), "+f"(acc[3])
        : "r"(a[0]), "r"(a[1]), "r"(a[2]), "r"(a[3]), "r"(b0), "r"(b1));
}
static __device__ __forceinline__ void ldsm4(unsigned* r, unsigned addr) {
    asm volatile(
        "ldmatrix.sync.aligned.m8n8.x4.shared.b16 {%0,%1,%2,%3}, [%4];\n"
        : "=r"(r[0]), "=r"(r[1]), "=r"(r[2]), "=r"(r[3]) : "r"(addr));
}

// ---------------------------------------------------------------------------
// ONE CTA per b, 256 threads (8 warps), 2 CTAs/SM (regs<=128).
// TC=16: 64-row chunks, DOUBLE-BUFFERED H/Q tiles.  C^T resident in registers
// (bfr 64 regs/warp, loaded once; its SMEM staging aliased by the buffers).
// scan(c+1) interleaved INSIDE GEMM(c)'s k-loop -> scan fully hidden.
// Warp tile: 32 rows (mwg) x 32 cols (nwg).  kappa-term in epilogue.
// ---------------------------------------------------------------------------
__global__ void __launch_bounds__(256, 2) gql_main(
    const float* __restrict__ inp,
    const float* __restrict__ phi_raw,  const float* __restrict__ chi_raw,
    const float* __restrict__ beta_raw, const float* __restrict__ kappa_raw,
    const float* __restrict__ C_raw,    float* __restrict__ out) {
    extern __shared__ char sm[];
    float2* sa_s    = (float2*)(sm + OFF_SA);
    float*  beta_s  = (float*)(sm + OFF_BETA);
    float*  kappa_s = (float*)(sm + OFF_KAPPA);
    float*  lpart   = (float*)(sm + OFF_LPART);
    __half* Ct      = (__half*)(sm + OFF_CT);

    const int b    = blockIdx.x;
    const int tid  = threadIdx.x;
    const int lane = tid & 31;
    const int w    = tid >> 5;
    const int g    = lane >> 2;
    const int tg   = lane & 3;
    const int pid  = min(max((int)nan0(__ldg(inp + (size_t)b * 9 + 8)), 0), P_DIM - 1);

    // scan assignment: a = tid>>6, d-pair (d0, d0+1)
    const int aidx = tid >> 6;
    const int d2   = tid & 63;
    const int d0   = d2 * 2;

    float phr0 = phi_raw[pid * D_DIM + d0], phr1 = phi_raw[pid * D_DIM + d0 + 1];
    float chr0 = chi_raw[pid * D_DIM + d0], chr1 = chi_raw[pid * D_DIM + d0 + 1];
    float phi0 = clipf(1.0f / (1.0f + expf(-phr0)), 0.01f, 0.99f);
    float phi1 = clipf(1.0f / (1.0f + expf(-phr1)), 0.01f, 0.99f);
    float chi0 = clipf(1.0f / (1.0f + expf(-chr0)), 0.01f, 0.99f);
    float chi1 = clipf(1.0f / (1.0f + expf(-chr1)), 0.01f, 0.99f);
    float omp0 = 1.0f - phi0, omp1 = 1.0f - phi1;
    float omc0 = 1.0f - chi0, omc1 = 1.0f - chi1;

    if (tid < 128) {
        float br = beta_raw[pid * D_DIM + tid];
        float sp = fmaxf(br, 0.0f) + log1pf(expf(-fabsf(br)));
        beta_s[tid]  = clipf(sp, 0.1f, 10.0f);
        kappa_s[tid] = clipf(kappa_raw[pid * D_DIM + tid], -10.0f, 10.0f);
    }
    // Stage Ct[e][d] = clip(C[d][e]) in the (aliased) buffer region
    for (int i = tid; i < D_DIM * D_DIM; i += 256) {
        int d = i >> 7, e = i & 127;
        Ct[e * 136 + d] = __float2half(clipf(C_raw[(size_t)pid * (D_DIM * D_DIM) + i],
                                             -10.0f, 10.0f));
    }
    __syncthreads();

    // resident B fragments: this warp's 32 e-cols, all 8 k-steps (64 regs)
    const int mwg = w & 1;     // 32-row group
    const int nwg = w >> 1;    // 32-col group
    unsigned bfr[2][8][4];
    {
        unsigned ct0 = smem_u32(Ct);
        int brow = (lane & 7) + ((lane & 16) ? 8 : 0);
        int bcol = (lane & 8) ? 16 : 0;
#pragma unroll
        for (int pr = 0; pr < 2; pr++) {
            unsigned base = ct0 + (unsigned)((nwg * 32 + pr * 16 + brow) * LDB + bcol);
#pragma unroll
            for (int ks = 0; ks < 8; ks++) ldsm4(bfr[pr][ks], base + ks * 32);
        }
    }
    __syncthreads();   // everyone done reading Ct before buffers overwrite it

    // sa chunks 0 and 1
    const float2* sa_src = g_SA + (size_t)b * T_DIM * A_DIM;
    if (tid < 128) sa_s[tid] = sa_src[tid];
    __syncthreads();

    // scan chunk 0 -> HS0/QS0 (standalone prologue)
    float q0 = 0.5f, q1 = 0.5f, h0 = 0.0f, h1 = 0.0f;
    {
        char* Hw = sm + OFF_HS0;
        char* Qw = sm + OFF_QS0;
#pragma unroll 4
        for (int tt = 0; tt < TC; tt++) {
            float2 sa = sa_s[tt * 4 + aidx];
            q0 = omp0 * q0 + phi0 * sa.x;
            q1 = omp1 * q1 + phi1 * sa.x;
            h0 = omc0 * h0 + chi0 * sa.y;
            h1 = omc1 * h1 + chi1 * sa.y;
            int row = tt * 4 + aidx;
            *(__half2*)(Hw + row * LDB + d2 * 4) = __floats2half2_rn(h0, h1);
            *(__half2*)(Qw + row * LDB + d2 * 4) = __floats2half2_rn(q0, q1);
        }
    }
    __syncthreads();

    // steady-state addresses
    const unsigned amt = smem_u32(sm + OFF_HS0)
        + (unsigned)((mwg * 32 + (lane & 15)) * LDB + ((lane & 16) ? 16 : 0));
    const unsigned qb0 = smem_u32(sm + OFF_QS0) + (unsigned)((mwg * 32 + lane) * LDB);
    const unsigned hb0 = smem_u32(sm + OFF_HS0) + (unsigned)((mwg * 32 + lane) * LDB);

    for (int c = 0; c < NCH; c++) {
        const int cb = c & 1;
        const unsigned rd = cb ? BUFD : 0u;     // GEMM/epilogue read side
        const unsigned wr = cb ? 0u : BUFD;     // scan write side
        const bool scan_on = (c + 1 < NCH);
        float2 nxt;
        const bool pf = (tid < 64) && (c + 2 < NCH);
        if (pf) nxt = __ldg(sa_src + (c + 2) * 64 + tid);

        char* Hw = sm + OFF_HS0 + wr;
        char* Qw = sm + OFF_QS0 + wr;
        const float2* sab = sa_s + (cb ^ 1) * 64;

        // ---- GEMM(c) with scan(c+1) interleaved in the k-loop ----
        float acc[2][4][4];
#pragma unroll
        for (int mt = 0; mt < 2; mt++)
#pragma unroll
            for (int nt = 0; nt < 4; nt++)
#pragma unroll
                for (int i = 0; i < 4; i++) acc[mt][nt][i] = 0.0f;

#pragma unroll
        for (int ks = 0; ks < 8; ks++) {
            unsigned af0[4], af1[4];
            ldsm4(af0, amt + rd + ks * 32);
            ldsm4(af1, amt + rd + 16 * LDB + ks * 32);
            if (scan_on) {
#pragma unroll
                for (int s2 = 0; s2 < 2; s2++) {
                    int tt = ks * 2 + s2;
                    float2 sa = sab[tt * 4 + aidx];
                    q0 = omp0 * q0 + phi0 * sa.x;
                    q1 = omp1 * q1 + phi1 * sa.x;
                    h0 = omc0 * h0 + chi0 * sa.y;
                    h1 = omc1 * h1 + chi1 * sa.y;
                    int row = tt * 4 + aidx;
                    *(__half2*)(Hw + row * LDB + d2 * 4) = __floats2half2_rn(h0, h1);
                    *(__half2*)(Qw + row * LDB + d2 * 4) = __floats2half2_rn(q0, q1);
                }
            }
#pragma unroll
            for (int nt = 0; nt < 4; nt++) {
                unsigned bx0 = bfr[nt >> 1][ks][2 * (nt & 1)];
                unsigned bx1 = bfr[nt >> 1][ks][2 * (nt & 1) + 1];
                mma16816(acc[0][nt], af0, bx0, bx1);
                mma16816(acc[1][nt], af1, bx0, bx1);
            }
        }
        if (pf) sa_s[cb * 64 + tid] = nxt;

        // ---- epilogue: logit partials over this warp's 32 cols ----
        float pl0[2] = {0.f, 0.f}, pl1[2] = {0.f, 0.f};
#pragma unroll
        for (int nt = 0; nt < 4; nt++) {
            int col = nwg * 32 + nt * 8;
            float2 bet = make_float2(beta_s[col + 2 * tg], beta_s[col + 2 * tg + 1]);
            float2 kap = make_float2(kappa_s[col + 2 * tg], kappa_s[col + 2 * tg + 1]);
            unsigned qf[4], hf[4];
            ldsm4(qf, qb0 + rd + (unsigned)(col * 2));
            ldsm4(hf, hb0 + rd + (unsigned)(col * 2));
#pragma unroll
            for (int mt = 0; mt < 2; mt++) {
                float2 qv0 = __half22float2(*(__half2*)&qf[2 * mt]);
                float2 qv1 = __half22float2(*(__half2*)&qf[2 * mt + 1]);
                float2 hv0 = __half22float2(*(__half2*)&hf[2 * mt]);
                float2 hv1 = __half22float2(*(__half2*)&hf[2 * mt + 1]);
                pl0[mt] += (acc[mt][nt][0] + bet.x) * qv0.x
                         + (acc[mt][nt][1] + bet.y) * qv0.y
                         + kap.x * hv0.x + kap.y * hv0.y;
                pl1[mt] += (acc[mt][nt][2] + bet.x) * qv1.x
                         + (acc[mt][nt][3] + bet.y) * qv1.y
                         + kap.x * hv1.x + kap.y * hv1.y;
            }
        }
#pragma unroll
        for (int mt = 0; mt < 2; mt++) {
            pl0[mt] += __shfl_xor_sync(0xffffffffu, pl0[mt], 1);
            pl0[mt] += __shfl_xor_sync(0xffffffffu, pl0[mt], 2);
            pl1[mt] += __shfl_xor_sync(0xffffffffu, pl1[mt], 1);
            pl1[mt] += __shfl_xor_sync(0xffffffffu, pl1[mt], 2);
            if (tg == 0) {
                int r0 = mwg * 32 + mt * 16 + g;
                lpart[nwg * 64 + r0]     = pl0[mt];
                lpart[nwg * 64 + r0 + 8] = pl1[mt];
            }
        }
        __syncthreads();   // lpart ready; scan writes of buf[cb^1] also visible

        if (tid < 64) {
            float lg = (lpart[tid] + lpart[64 + tid])
                     + (lpart[128 + tid] + lpart[192 + tid]);
            int tt = tid >> 2, a = tid & 3;
            out[((size_t)(c * TC + tt) * B_DIM + b) * A_DIM + a] = lg;
        }
        __syncthreads();   // lpart consumed; sa slot + buffers safe to reuse
    }

    // final q, h: shape (B, A, D)
    float* out_q = out + (size_t)NLOGIT;
    float* out_h = out_q + B_DIM * A_DIM * D_DIM;
    ((float2*)out_q)[(b * A_DIM + aidx) * 64 + d2] = make_float2(q0, q1);
    ((float2*)out_h)[(b * A_DIM + aidx) * 64 + d2] = make_float2(h0, h1);
}

extern "C" void kernel_launch(void* const* d_in, const int* in_sizes, int n_in,
                              void* d_out, int out_size) {
    const float* inp       = (const float*)d_in[0];
    const float* phi_raw   = (const float*)d_in[1];
    const float* chi_raw   = (const float*)d_in[2];
    const float* beta_raw  = (const float*)d_in[3];
    const float* kappa_raw = (const float*)d_in[4];
    const float* C_raw     = (const float*)d_in[5];
    float* out = (float*)d_out;

    cudaFuncSetAttribute(gql_main, cudaFuncAttributeMaxDynamicSharedMemorySize,
                         SMEM_BYTES);

    prep_kernel<<<(T_DIM * B_DIM + 255) / 256, 256>>>(inp);
    gql_main<<<B_DIM, 256, SMEM_BYTES>>>(inp, phi_raw, chi_raw, beta_raw,
                                         kappa_raw, C_raw, out);
}

// round 13
// speedup vs baseline: 1.1947x; 1.1377x over previous
#include <cuda_runtime.h>
#include <cuda_fp16.h>
#include <math.h>

#define T_DIM 2048
#define B_DIM 1024
#define A_DIM 4
#define D_DIM 128
#define P_DIM 256
#define TC    16
#define NCH   (T_DIM / TC)     // 128 chunks of 64 rows
#define LDB   272              // tile row stride in bytes (136 halves)
#define NLOGIT (T_DIM * B_DIM * A_DIM)

// SMEM layout (bytes) — total 73728 => 3 CTAs/SM
#define OFF_SA    0            // 2 x 64 float2   [0,1024)
#define OFF_BETA  1024         // 128 floats      [1024,1536)
#define OFF_KAPPA 1536         // 128 floats      [1536,2048)
#define OFF_LPART 2048         // 4 x 64 floats   [2048,3072)
#define OFF_CT    4096         // 128 x 272 = 34816  [4096,38912)
#define OFF_HS    38912        // 64 x 272 = 17408   [38912,56320)
#define OFF_QS    56320        // 17408              [56320,73728)
#define SMEM_BYTES 73728

// scratch: per (b,t,a): (s = r*a, a)
__device__ float2 g_SA[(size_t)B_DIM * T_DIM * A_DIM];

static __device__ __forceinline__ float nan0(float x) { return (x == x) ? x : 0.0f; }
static __device__ __forceinline__ float clipf(float x, float lo, float hi) {
    return fminf(fmaxf(x, lo), hi);
}
static __device__ __forceinline__ unsigned smem_u32(const void* p) {
    return (unsigned)__cvta_generic_to_shared(p);
}

__global__ void prep_kernel(const float* __restrict__ inp) {
    int gid = blockIdx.x * blockDim.x + threadIdx.x;
    if (gid >= T_DIM * B_DIM) return;
    int b = gid % B_DIM;
    int t = gid / B_DIM;
    const float* row = inp + ((size_t)t * B_DIM + b) * 9;
    float2* o = g_SA + ((size_t)b * T_DIM + t) * A_DIM;
#pragma unroll
    for (int a = 0; a < A_DIM; a++) {
        float act = nan0(row[a]);
        float r   = nan0(row[4 + a]);
        o[a] = make_float2(r * act, act);
    }
}

static __device__ __forceinline__ void mma16816(float* acc, const unsigned* a,
                                                unsigned b0, unsigned b1) {
    asm volatile(
        "mma.sync.aligned.m16n8k16.row.col.f32.f16.f16.f32 "
        "{%0,%1,%2,%3}, {%4,%5,%6,%7}, {%8,%9}, {%0,%1,%2,%3};\n"
        : "+f"(acc[0]), "+f"(acc[1]), "+f"(acc[2]), "+f"(acc[3])
        : "r"(a[0]), "r"(a[1]), "r"(a[2]), "r"(a[3]), "r"(b0), "r"(b1));
}
static __device__ __forceinline__ void ldsm4(unsigned* r, unsigned addr) {
    asm volatile(
        "ldmatrix.sync.aligned.m8n8.x4.shared.b16 {%0,%1,%2,%3}, [%4];\n"
        : "=r"(r[0]), "=r"(r[1]), "=r"(r[2]), "=r"(r[3]) : "r"(addr));
}

// ---------------------------------------------------------------------------
// ONE CTA per b, 256 threads (8 warps), 3 CTAs/SM (smem 72KB, regs<=85).
// TC=16 (64-row chunks), SINGLE-buffered tiles, phased scan -> GEMM.
// Warp tile 32 rows (mwg=w&1) x 32 cols (nwg=w>>1); B from SMEM; kappa
// in the epilogue.  Cross-CTA phase drift provides the overlap.
// ---------------------------------------------------------------------------
__global__ void __launch_bounds__(256, 3) gql_main(
    const float* __restrict__ inp,
    const float* __restrict__ phi_raw,  const float* __restrict__ chi_raw,
    const float* __restrict__ beta_raw, const float* __restrict__ kappa_raw,
    const float* __restrict__ C_raw,    float* __restrict__ out) {
    extern __shared__ char sm[];
    float2* sa_s    = (float2*)(sm + OFF_SA);
    float*  beta_s  = (float*)(sm + OFF_BETA);
    float*  kappa_s = (float*)(sm + OFF_KAPPA);
    float*  lpart   = (float*)(sm + OFF_LPART);
    __half* Ct      = (__half*)(sm + OFF_CT);

    const int b    = blockIdx.x;
    const int tid  = threadIdx.x;
    const int lane = tid & 31;
    const int w    = tid >> 5;
    const int g    = lane >> 2;
    const int tg   = lane & 3;
    const int pid  = min(max((int)nan0(__ldg(inp + (size_t)b * 9 + 8)), 0), P_DIM - 1);

    // scan assignment: a = tid>>6, d-pair (d0, d0+1)
    const int aidx = tid >> 6;
    const int d2   = tid & 63;
    const int d0   = d2 * 2;

    float phr0 = phi_raw[pid * D_DIM + d0], phr1 = phi_raw[pid * D_DIM + d0 + 1];
    float chr0 = chi_raw[pid * D_DIM + d0], chr1 = chi_raw[pid * D_DIM + d0 + 1];
    float phi0 = clipf(1.0f / (1.0f + expf(-phr0)), 0.01f, 0.99f);
    float phi1 = clipf(1.0f / (1.0f + expf(-phr1)), 0.01f, 0.99f);
    float chi0 = clipf(1.0f / (1.0f + expf(-chr0)), 0.01f, 0.99f);
    float chi1 = clipf(1.0f / (1.0f + expf(-chr1)), 0.01f, 0.99f);
    float omp0 = 1.0f - phi0, omp1 = 1.0f - phi1;
    float omc0 = 1.0f - chi0, omc1 = 1.0f - chi1;

    if (tid < 128) {
        float br = beta_raw[pid * D_DIM + tid];
        float sp = fmaxf(br, 0.0f) + log1pf(expf(-fabsf(br)));
        beta_s[tid]  = clipf(sp, 0.1f, 10.0f);
        kappa_s[tid] = clipf(kappa_raw[pid * D_DIM + tid], -10.0f, 10.0f);
    }
    // Ct[e][d] = clip(C[d][e])  (col-major B operand), stays in SMEM
    for (int i = tid; i < D_DIM * D_DIM; i += 256) {
        int d = i >> 7, e = i & 127;
        Ct[e * 136 + d] = __float2half(clipf(C_raw[(size_t)pid * (D_DIM * D_DIM) + i],
                                             -10.0f, 10.0f));
    }

    // preload sa chunk 0 into buf 0
    const float2* sa_src = g_SA + (size_t)b * T_DIM * A_DIM;
    if (tid < 64) sa_s[tid] = sa_src[tid];
    __syncthreads();

    // warp tiling + fragment addresses
    const int mwg = w & 1;
    const int nwg = w >> 1;
    const unsigned amt = smem_u32(sm + OFF_HS)
        + (unsigned)((mwg * 32 + (lane & 15)) * LDB + ((lane & 16) ? 16 : 0));
    const unsigned bb = smem_u32(Ct)
        + (unsigned)((nwg * 32 + (lane & 7) + ((lane & 16) ? 8 : 0)) * LDB
                     + ((lane & 8) ? 16 : 0));
    const unsigned hb = smem_u32(sm + OFF_HS) + (unsigned)((mwg * 32 + lane) * LDB);

    float q0 = 0.5f, q1 = 0.5f, h0 = 0.0f, h1 = 0.0f;

    for (int c = 0; c < NCH; c++) {
        const int cb = c & 1;
        float2 nxt;
        const bool pf = (tid < 64) && (c + 1 < NCH);
        if (pf) nxt = __ldg(sa_src + (c + 1) * 64 + tid);

        // ---- scan phase: fp32 state -> f16 tiles ----
        {
            char* Hw = sm + OFF_HS;
            char* Qw = sm + OFF_QS;
            const float2* sab = sa_s + cb * 64;
#pragma unroll 4
            for (int tt = 0; tt < TC; tt++) {
                float2 sa = sab[tt * 4 + aidx];
                q0 = omp0 * q0 + phi0 * sa.x;
                q1 = omp1 * q1 + phi1 * sa.x;
                h0 = omc0 * h0 + chi0 * sa.y;
                h1 = omc1 * h1 + chi1 * sa.y;
                int row = tt * 4 + aidx;
                *(__half2*)(Hw + row * LDB + d2 * 4) = __floats2half2_rn(h0, h1);
                *(__half2*)(Qw + row * LDB + d2 * 4) = __floats2half2_rn(q0, q1);
            }
        }
        if (pf) sa_s[(cb ^ 1) * 64 + tid] = nxt;
        __syncthreads();   // tiles + next sa ready

        // ---- GEMM: 32x32 warp tile over this chunk's 64x128 U ----
        float acc[2][4][4];
#pragma unroll
        for (int mt = 0; mt < 2; mt++)
#pragma unroll
            for (int nt = 0; nt < 4; nt++)
#pragma unroll
                for (int i = 0; i < 4; i++) acc[mt][nt][i] = 0.0f;

#pragma unroll
        for (int ks = 0; ks < 8; ks++) {
            unsigned af0[4], af1[4], bf[4];
            ldsm4(af0, amt + ks * 32);
            ldsm4(af1, amt + 16 * LDB + ks * 32);
            ldsm4(bf, bb + ks * 32);
            mma16816(acc[0][0], af0, bf[0], bf[1]);
            mma16816(acc[0][1], af0, bf[2], bf[3]);
            mma16816(acc[1][0], af1, bf[0], bf[1]);
            mma16816(acc[1][1], af1, bf[2], bf[3]);
            ldsm4(bf, bb + 16 * LDB + ks * 32);
            mma16816(acc[0][2], af0, bf[0], bf[1]);
            mma16816(acc[0][3], af0, bf[2], bf[3]);
            mma16816(acc[1][2], af1, bf[0], bf[1]);
            mma16816(acc[1][3], af1, bf[2], bf[3]);
        }

        // ---- epilogue: logit partials over this warp's 32 cols ----
        float pl0[2] = {0.f, 0.f}, pl1[2] = {0.f, 0.f};
#pragma unroll
        for (int nt = 0; nt < 4; nt++) {
            int col = nwg * 32 + nt * 8;
            float2 bet = make_float2(beta_s[col + 2 * tg], beta_s[col + 2 * tg + 1]);
            float2 kap = make_float2(kappa_s[col + 2 * tg], kappa_s[col + 2 * tg + 1]);
            unsigned qf[4], hf[4];
            ldsm4(qf, hb + (OFF_QS - OFF_HS) + (unsigned)(col * 2));
            ldsm4(hf, hb + (unsigned)(col * 2));
#pragma unroll
            for (int mt = 0; mt < 2; mt++) {
                float2 qv0 = __half22float2(*(__half2*)&qf[2 * mt]);
                float2 qv1 = __half22float2(*(__half2*)&qf[2 * mt + 1]);
                float2 hv0 = __half22float2(*(__half2*)&hf[2 * mt]);
                float2 hv1 = __half22float2(*(__half2*)&hf[2 * mt + 1]);
                pl0[mt] += (acc[mt][nt][0] + bet.x) * qv0.x
                         + (acc[mt][nt][1] + bet.y) * qv0.y
                         + kap.x * hv0.x + kap.y * hv0.y;
                pl1[mt] += (acc[mt][nt][2] + bet.x) * qv1.x
                         + (acc[mt][nt][3] + bet.y) * qv1.y
                         + kap.x * hv1.x + kap.y * hv1.y;
            }
        }
#pragma unroll
        for (int mt = 0; mt < 2; mt++) {
            pl0[mt] += __shfl_xor_sync(0xffffffffu, pl0[mt], 1);
            pl0[mt] += __shfl_xor_sync(0xffffffffu, pl0[mt], 2);
            pl1[mt] += __shfl_xor_sync(0xffffffffu, pl1[mt], 1);
            pl1[mt] += __shfl_xor_sync(0xffffffffu, pl1[mt], 2);
            if (tg == 0) {
                int r0 = mwg * 32 + mt * 16 + g;
                lpart[nwg * 64 + r0]     = pl0[mt];
                lpart[nwg * 64 + r0 + 8] = pl1[mt];
            }
        }
        __syncthreads();   // lpart ready; tiles consumed (safe for next scan)

        if (tid < 64) {    // combine 4 col-group partials, store logits
            float lg = (lpart[tid] + lpart[64 + tid])
                     + (lpart[128 + tid] + lpart[192 + tid]);
            int tt = tid >> 2, a = tid & 3;
            out[((size_t)(c * TC + tt) * B_DIM + b) * A_DIM + a] = lg;
        }
        // no barrier needed here: next lpart write happens only after the
        // next __syncthreads() (all threads, incl. tid<64, must arrive)
    }

    // final q, h: shape (B, A, D)
    float* out_q = out + (size_t)NLOGIT;
    float* out_h = out_q + B_DIM * A_DIM * D_DIM;
    ((float2*)out_q)[(b * A_DIM + aidx) * 64 + d2] = make_float2(q0, q1);
    ((float2*)out_h)[(b * A_DIM + aidx) * 64 + d2] = make_float2(h0, h1);
}

extern "C" void kernel_launch(void* const* d_in, const int* in_sizes, int n_in,
                              void* d_out, int out_size) {
    const float* inp       = (const float*)d_in[0];
    const float* phi_raw   = (const float*)d_in[1];
    const float* chi_raw   = (const float*)d_in[2];
    const float* beta_raw  = (const float*)d_in[3];
    const float* kappa_raw = (const float*)d_in[4];
    const float* C_raw     = (const float*)d_in[5];
    float* out = (float*)d_out;

    cudaFuncSetAttribute(gql_main, cudaFuncAttributeMaxDynamicSharedMemorySize,
                         SMEM_BYTES);

    prep_kernel<<<(T_DIM * B_DIM + 255) / 256, 256>>>(inp);
    gql_main<<<B_DIM, 256, SMEM_BYTES>>>(inp, phi_raw, chi_raw, beta_raw,
                                         kappa_raw, C_raw, out);
}